// round 15
// baseline (speedup 1.0000x reference)
#include <cuda_runtime.h>
#include <math.h>
#include <stdint.h>

#define T_TOK   8192
#define D_MODEL 1024
#define D_FF    4096
#define N_EXP   8
#define EXP_BASE 8192
#define MAX_ROWS 25600
#define NRB (MAX_ROWS / 128)   // 200

// ---------------- device scratch (static) ----------------
__device__ __align__(128) signed char d_xq1[(size_t)T_TOK * D_MODEL];
__device__ __align__(128) signed char d_xq0[(size_t)T_TOK * D_MODEL];
__device__ float d_sx[T_TOK];
__device__ __align__(128) signed char d_w1q1[(size_t)9 * D_FF * D_MODEL];  // [g][N][K]
__device__ __align__(128) signed char d_w1q0[(size_t)9 * D_FF * D_MODEL];
__device__ __align__(128) signed char d_w2q1[(size_t)9 * D_MODEL * D_FF];
__device__ __align__(128) signed char d_w2q0[(size_t)9 * D_MODEL * D_FF];
__device__ float d_sw1[9 * D_FF],    d_sw1i[9 * D_FF];
__device__ float d_sw2[9 * D_MODEL], d_sw2i[9 * D_MODEL];
__device__ __align__(128) float d_hf[(size_t)MAX_ROWS * D_FF];
__device__ __align__(128) signed char d_hq1[(size_t)MAX_ROWS * D_FF];
__device__ __align__(128) signed char d_hq0[(size_t)MAX_ROWS * D_FF];
__device__ float d_sh[MAX_ROWS];
__device__ __align__(128) float d_y[(size_t)MAX_ROWS * D_MODEL];
__device__ int   d_row_tok[MAX_ROWS];
__device__ int   d_e0[T_TOK], d_e1[T_TOK];
__device__ float d_w0[T_TOK], d_w1v[T_TOK];
__device__ int   d_slot0[T_TOK], d_slot1[T_TOK];
__device__ int   d_counts[N_EXP];
__device__ int   d_fill[N_EXP];
__device__ int   d_est[N_EXP + 1];

// ---------------- helpers ----------------
__device__ __forceinline__ uint32_t smem_u32(const void* p) {
    uint32_t a;
    asm("{ .reg .u64 t; cvta.to.shared.u64 t, %1; cvt.u32.u64 %0, t; }" : "=r"(a) : "l"(p));
    return a;
}
__device__ __forceinline__ void cpa(uint32_t d, const void* s, int sz) {
    asm volatile("cp.async.cg.shared.global [%0], [%1], 16, %2;" :: "r"(d), "l"(s), "r"(sz) : "memory");
}
#define CP_COMMIT() asm volatile("cp.async.commit_group;" ::: "memory")
#define CP_WAIT1()  asm volatile("cp.async.wait_group 1;" ::: "memory")
#define CP_WAIT0()  asm volatile("cp.async.wait_group 0;" ::: "memory")

__device__ __forceinline__ uint4 ldm4(uint32_t a) {
    uint4 r;
    asm volatile("ldmatrix.sync.aligned.m8n8.x4.shared.b16 {%0,%1,%2,%3}, [%4];"
                 : "=r"(r.x), "=r"(r.y), "=r"(r.z), "=r"(r.w) : "r"(a));
    return r;
}
__device__ __forceinline__ void imma(int* c, const uint4& a, uint32_t b0, uint32_t b1) {
    asm volatile(
        "mma.sync.aligned.m16n8k32.row.col.s32.s8.s8.s32 "
        "{%0,%1,%2,%3},{%4,%5,%6,%7},{%8,%9},{%0,%1,%2,%3};"
        : "+r"(c[0]), "+r"(c[1]), "+r"(c[2]), "+r"(c[3])
        : "r"(a.x), "r"(a.y), "r"(a.z), "r"(a.w), "r"(b0), "r"(b1));
}
__device__ __forceinline__ float gelu_exact(float v) {
    return 0.5f * v * (1.0f + erff(v * 0.70710678118654752440f));
}
// quantize one float to two int8 digits given inv = 16256/amax
__device__ __forceinline__ void quant2(float f, float inv, int& a1, int& a0) {
    float qf = rintf(f * inv);
    int qi = (int)qf;
    int d1 = (int)rintf(qf * 0.0078125f);
    if (d1 > 127) d1 = 127;
    if (d1 < -127) d1 = -127;
    a1 = d1;
    a0 = qi - (d1 << 7);
}

// smem stage: A1[0,16K) A0[16K,32K) B1[32K,48K) B0[48K,64K); 3 stages
// rows are 128 bytes = 128 int8 of K; K-chunk = 128.
#define STAGE_SZ 65536
#define GEMM_SMEM (3 * STAGE_SZ)   // 192 KB

// ---------------- init / router / offsets / scatter ----------------
__global__ void init_kernel() {
    int i = blockIdx.x * blockDim.x + threadIdx.x;
    if (i < N_EXP) { d_counts[i] = 0; d_fill[i] = 0; }
    if (i < MAX_ROWS) d_row_tok[i] = (i < T_TOK) ? i : -1;
}

__global__ void router_kernel(const float* __restrict__ x,
                              const float* __restrict__ rw,
                              const float* __restrict__ rb) {
    int gid = blockIdx.x * blockDim.x + threadIdx.x;
    int t = gid >> 5, lane = gid & 31;
    if (t >= T_TOK) return;
    const float* xr = x + (size_t)t * D_MODEL;
    float acc[N_EXP];
#pragma unroll
    for (int e = 0; e < N_EXP; e++) acc[e] = 0.0f;
    for (int k = lane; k < D_MODEL; k += 32) {
        float xv = xr[k];
        const float4* w4 = (const float4*)(rw + (size_t)k * N_EXP);
        float4 wa = w4[0], wb = w4[1];
        acc[0] += xv * wa.x; acc[1] += xv * wa.y; acc[2] += xv * wa.z; acc[3] += xv * wa.w;
        acc[4] += xv * wb.x; acc[5] += xv * wb.y; acc[6] += xv * wb.z; acc[7] += xv * wb.w;
    }
#pragma unroll
    for (int off = 16; off > 0; off >>= 1)
#pragma unroll
        for (int e = 0; e < N_EXP; e++) acc[e] += __shfl_xor_sync(0xFFFFFFFFu, acc[e], off);
    if (lane == 0) {
        float l[N_EXP], m = -1e30f;
#pragma unroll
        for (int e = 0; e < N_EXP; e++) { l[e] = acc[e] + rb[e]; m = fmaxf(m, l[e]); }
        float p[N_EXP], s = 0.0f;
#pragma unroll
        for (int e = 0; e < N_EXP; e++) { p[e] = __expf(l[e] - m); s += p[e]; }
        float inv = 1.0f / s;
#pragma unroll
        for (int e = 0; e < N_EXP; e++) p[e] *= inv;
        int i0 = 0; float p0 = p[0];
#pragma unroll
        for (int e = 1; e < N_EXP; e++) if (p[e] > p0) { p0 = p[e]; i0 = e; }
        int i1 = -1; float p1 = -1e30f;
#pragma unroll
        for (int e = 0; e < N_EXP; e++) { if (e == i0) continue; if (p[e] > p1) { p1 = p[e]; i1 = e; } }
        float denom = p0 + p1 + 1e-9f;
        d_e0[t] = i0; d_e1[t] = i1;
        d_w0[t] = p0 / denom; d_w1v[t] = p1 / denom;
        atomicAdd(&d_counts[i0], 1);
        atomicAdd(&d_counts[i1], 1);
    }
}

__global__ void offsets_kernel() {
    if (threadIdx.x == 0 && blockIdx.x == 0) {
        int run = EXP_BASE;
#pragma unroll
        for (int e = 0; e < N_EXP; e++) { d_est[e] = run; run += (d_counts[e] + 127) & ~127; }
        d_est[N_EXP] = run;
    }
}

__global__ void scatter_kernel() {
    int t = blockIdx.x * blockDim.x + threadIdx.x;
    if (t >= T_TOK) return;
    int e0 = d_e0[t];
    int r0 = d_est[e0] + atomicAdd(&d_fill[e0], 1);
    d_row_tok[r0] = t; d_slot0[t] = r0;
    int e1 = d_e1[t];
    int r1 = d_est[e1] + atomicAdd(&d_fill[e1], 1);
    d_row_tok[r1] = t; d_slot1[t] = r1;
}

// ---------------- quantize x: per-token row scale, 2 int8 digits ----------------
__global__ void quant_x_kernel(const float* __restrict__ x) {
    int t = blockIdx.x * (blockDim.x >> 5) + (threadIdx.x >> 5);
    int lane = threadIdx.x & 31;
    if (t >= T_TOK) return;
    const float4* xr = (const float4*)(x + (size_t)t * D_MODEL);
    float4 v[8];
    float m = 0.0f;
#pragma unroll
    for (int j = 0; j < 8; j++) {
        v[j] = xr[lane + j * 32];
        m = fmaxf(m, fmaxf(fmaxf(fabsf(v[j].x), fabsf(v[j].y)), fmaxf(fabsf(v[j].z), fabsf(v[j].w))));
    }
#pragma unroll
    for (int off = 16; off > 0; off >>= 1) m = fmaxf(m, __shfl_xor_sync(0xFFFFFFFFu, m, off));
    float inv = (m > 0.0f) ? (16256.0f / m) : 0.0f;
    if (lane == 0) d_sx[t] = m * (1.0f / 16256.0f);
    uint32_t* o1 = (uint32_t*)(d_xq1 + (size_t)t * D_MODEL);
    uint32_t* o0 = (uint32_t*)(d_xq0 + (size_t)t * D_MODEL);
#pragma unroll
    for (int j = 0; j < 8; j++) {
        float f[4] = { v[j].x, v[j].y, v[j].z, v[j].w };
        uint32_t u1 = 0, u0 = 0;
#pragma unroll
        for (int e = 0; e < 4; e++) {
            int a1, a0; quant2(f[e], inv, a1, a0);
            u1 |= ((uint32_t)(a1 & 0xff)) << (8 * e);
            u0 |= ((uint32_t)(a0 & 0xff)) << (8 * e);
        }
        o1[lane + j * 32] = u1;
        o0[lane + j * 32] = u0;
    }
}

// ---------------- weight column max (per output col n) ----------------
__global__ void colmax_kernel(const float* __restrict__ sw, const float* __restrict__ ew,
                              float* __restrict__ scale, float* __restrict__ inv, int K, int N) {
    int g = blockIdx.y;
    const float* W = (g == 0) ? sw : (ew + (size_t)(g - 1) * K * N);
    int n = blockIdx.x * 256 + threadIdx.x;
    float m = 0.0f;
    for (int k = 0; k < K; k++) m = fmaxf(m, fabsf(W[(size_t)k * N + n]));
    scale[g * N + n] = m * (1.0f / 16256.0f);
    inv[g * N + n]   = (m > 0.0f) ? (16256.0f / m) : 0.0f;
}

// ---------------- weight quantize + transpose: [K][N] fp32 -> [N][K] int8 x2 ----------------
__global__ __launch_bounds__(256)
void quantw_kernel(const float* __restrict__ sw, const float* __restrict__ ew,
                   const float* __restrict__ winv,
                   signed char* __restrict__ q1, signed char* __restrict__ q0,
                   int K, int N) {
    __shared__ float t[64][65];
    int g = blockIdx.z;
    const float* W = (g == 0) ? sw : (ew + (size_t)(g - 1) * K * N);
    int k0 = blockIdx.y * 64, nn0 = blockIdx.x * 64;
    int tid = threadIdx.x;
#pragma unroll
    for (int j = 0; j < 4; j++) {
        int row = (tid >> 4) + j * 16, col = (tid & 15) * 4;
        float4 v = *(const float4*)(W + (size_t)(k0 + row) * N + nn0 + col);
        t[row][col] = v.x; t[row][col + 1] = v.y; t[row][col + 2] = v.z; t[row][col + 3] = v.w;
    }
    __syncthreads();
    int n = tid >> 2, ks = (tid & 3) * 16;
    float inv = winv[g * N + nn0 + n];
    uint32_t u1[4] = {0, 0, 0, 0}, u0[4] = {0, 0, 0, 0};
#pragma unroll
    for (int j = 0; j < 16; j++) {
        int a1, a0; quant2(t[ks + j][n], inv, a1, a0);
        u1[j >> 2] |= ((uint32_t)(a1 & 0xff)) << ((j & 3) * 8);
        u0[j >> 2] |= ((uint32_t)(a0 & 0xff)) << ((j & 3) * 8);
    }
    size_t o = ((size_t)g * N + nn0 + n) * K + k0 + ks;
    *(uint4*)(q1 + o) = make_uint4(u1[0], u1[1], u1[2], u1[3]);
    *(uint4*)(q0 + o) = make_uint4(u0[0], u0[1], u0[2], u0[3]);
}

// ---------------- quantize h rows ----------------
__global__ __launch_bounds__(256)
void quant_h_kernel() {
    int row = blockIdx.x;
    if (row >= d_est[N_EXP]) return;
    int tid = threadIdx.x;
    const float4* hr = (const float4*)(d_hf + (size_t)row * D_FF);
    float4 v[4];
    float m = 0.0f;
#pragma unroll
    for (int j = 0; j < 4; j++) {
        v[j] = hr[tid + j * 256];
        m = fmaxf(m, fmaxf(fmaxf(fabsf(v[j].x), fabsf(v[j].y)), fmaxf(fabsf(v[j].z), fabsf(v[j].w))));
    }
    __shared__ float red[8];
#pragma unroll
    for (int off = 16; off > 0; off >>= 1) m = fmaxf(m, __shfl_xor_sync(0xFFFFFFFFu, m, off));
    if ((tid & 31) == 0) red[tid >> 5] = m;
    __syncthreads();
    if (tid < 32) {
        float mm = (tid < 8) ? red[tid] : 0.0f;
#pragma unroll
        for (int off = 4; off > 0; off >>= 1) mm = fmaxf(mm, __shfl_xor_sync(0xFFFFFFFFu, mm, off));
        if (tid == 0) red[0] = mm;
    }
    __syncthreads();
    float amax = red[0];
    float inv = (amax > 0.0f) ? (16256.0f / amax) : 0.0f;
    if (tid == 0) d_sh[row] = amax * (1.0f / 16256.0f);
    uint32_t* o1 = (uint32_t*)(d_hq1 + (size_t)row * D_FF);
    uint32_t* o0 = (uint32_t*)(d_hq0 + (size_t)row * D_FF);
#pragma unroll
    for (int j = 0; j < 4; j++) {
        float f[4] = { v[j].x, v[j].y, v[j].z, v[j].w };
        uint32_t u1 = 0, u0 = 0;
#pragma unroll
        for (int e = 0; e < 4; e++) {
            int a1, a0; quant2(f[e], inv, a1, a0);
            u1 |= ((uint32_t)(a1 & 0xff)) << (8 * e);
            u0 |= ((uint32_t)(a0 & 0xff)) << (8 * e);
        }
        o1[tid + j * 256] = u1;
        o0[tid + j * 256] = u0;
    }
}

// ---------------- GEMM compute core (128x128 tile, 16 warps, warp 32x32) ----------------
// rows = 128B = 128 int8 K; kk = k32 group; byte addressing identical to bf16 k16 version.
#define GEMM_COMPUTE(stbase)                                                          \
    {                                                                                 \
        uint32_t aB = (stbase) + warp_m * (32 * 128);                                 \
        uint32_t bB = (stbase) + 32768 + warp_n * (32 * 128);                         \
        _Pragma("unroll")                                                             \
        for (int kk = 0; kk < 4; kk++) {                                              \
            uint4 A1[2], A0[2], B1f[2], B0f[2];                                       \
            _Pragma("unroll")                                                         \
            for (int mi = 0; mi < 2; mi++) {                                          \
                int rl = mi * 16 + (lane & 15);                                       \
                int ck = kk * 2 + (lane >> 4);                                        \
                uint32_t off = rl * 128 + ((ck ^ (rl & 7)) << 4);                     \
                A1[mi] = ldm4(aB + off);                                              \
                A0[mi] = ldm4(aB + off + 16384);                                      \
            }                                                                         \
            _Pragma("unroll")                                                         \
            for (int p = 0; p < 2; p++) {                                             \
                int nl = p * 16 + ((lane >> 4) << 3) + (lane & 7);                    \
                int ck = kk * 2 + ((lane >> 3) & 1);                                  \
                uint32_t off = nl * 128 + ((ck ^ (nl & 7)) << 4);                     \
                B1f[p] = ldm4(bB + off);                                              \
                B0f[p] = ldm4(bB + off + 16384);                                      \
            }                                                                         \
            _Pragma("unroll")                                                         \
            for (int mi = 0; mi < 2; mi++)                                            \
                _Pragma("unroll")                                                     \
                for (int p = 0; p < 2; p++) {                                         \
                    imma(S1[mi][2 * p],     A1[mi], B1f[p].x, B1f[p].y);              \
                    imma(S1[mi][2 * p + 1], A1[mi], B1f[p].z, B1f[p].w);              \
                }                                                                     \
            _Pragma("unroll")                                                         \
            for (int mi = 0; mi < 2; mi++)                                            \
                _Pragma("unroll")                                                     \
                for (int p = 0; p < 2; p++) {                                         \
                    imma(S2[mi][2 * p],     A1[mi], B0f[p].x, B0f[p].y);              \
                    imma(S2[mi][2 * p + 1], A1[mi], B0f[p].z, B0f[p].w);              \
                }                                                                     \
            _Pragma("unroll")                                                         \
            for (int mi = 0; mi < 2; mi++)                                            \
                _Pragma("unroll")                                                     \
                for (int p = 0; p < 2; p++) {                                         \
                    imma(S2[mi][2 * p],     A0[mi], B1f[p].x, B1f[p].y);              \
                    imma(S2[mi][2 * p + 1], A0[mi], B1f[p].z, B1f[p].w);              \
                }                                                                     \
        }                                                                             \
    }

// ---------------- GEMM1: h = gelu(gather(x) @ W1_g + b1_g) (int8 digits) ----------------
__global__ __launch_bounds__(512, 1)
void gemm1_imma(const float* __restrict__ sb1, const float* __restrict__ eb1) {
    extern __shared__ char sm[];
    __shared__ int   s_tok[128];
    __shared__ float s_sx[128];
    __shared__ float s_bias[128];
    __shared__ float s_sc[128];
    uint32_t smb = smem_u32(sm);
    int tid = threadIdx.x, lane = tid & 31, wid = tid >> 5;
    int warp_m = wid & 3, warp_n = wid >> 2;   // 4 x 4
    int rb = blockIdx.y, nb = blockIdx.x;
    int row0 = rb * 128, n0 = nb * 128;
    if (row0 >= d_est[N_EXP]) return;
    int g = 0;
    if (row0 >= EXP_BASE) {
        int e = 0;
#pragma unroll
        for (int i = 1; i < N_EXP; i++) if (row0 >= d_est[i]) e = i;
        g = e + 1;
    }
    const float* bias = (g == 0) ? sb1 : (eb1 + (size_t)(g - 1) * D_FF);
    if (tid < 128) {
        int tok = d_row_tok[row0 + tid];
        s_tok[tid] = tok;
        s_sx[tid] = (tok >= 0) ? d_sx[tok] : 0.0f;
        s_bias[tid] = bias[n0 + tid];
        s_sc[tid] = d_sw1[g * D_FF + n0 + tid];
    }
    __syncthreads();

    const signed char* wq1 = d_w1q1 + ((size_t)g * D_FF + n0) * D_MODEL;
    const signed char* wq0 = d_w1q0 + ((size_t)g * D_FF + n0) * D_MODEL;

    int S1[2][4][4], S2[2][4][4];
#pragma unroll
    for (int a = 0; a < 2; a++)
#pragma unroll
        for (int b = 0; b < 4; b++)
#pragma unroll
            for (int c = 0; c < 4; c++) { S1[a][b][c] = 0; S2[a][b][c] = 0; }

    auto load_stage = [&](int i, int st) {
        uint32_t bb = smb + st * STAGE_SZ;
#pragma unroll
        for (int j = 0; j < 2; j++) {
            int ch = tid * 2 + j; int r = ch >> 3, c = ch & 7;
            int tok = s_tok[r];
            int sz = (tok >= 0) ? 16 : 0;
            size_t so = (size_t)(tok < 0 ? 0 : tok) * D_MODEL + i * 128 + c * 16;
            uint32_t dsw = bb + r * 128 + ((c ^ (r & 7)) << 4);
            cpa(dsw, d_xq1 + so, sz);
            cpa(dsw + 16384, d_xq0 + so, sz);
        }
#pragma unroll
        for (int j = 0; j < 2; j++) {
            int ch = tid * 2 + j; int r = ch >> 3, c = ch & 7;
            size_t so = (size_t)r * D_MODEL + i * 128 + c * 16;
            uint32_t dsw = bb + 32768 + r * 128 + ((c ^ (r & 7)) << 4);
            cpa(dsw, wq1 + so, 16);
            cpa(dsw + 16384, wq0 + so, 16);
        }
        CP_COMMIT();
    };

    const int NCH = D_MODEL / 128;  // 8
    load_stage(0, 0);
    load_stage(1, 1);
    for (int i = 0; i < NCH; i++) {
        int st = i % 3;
        if (i + 1 < NCH) CP_WAIT1(); else CP_WAIT0();
        __syncthreads();
        if (i + 2 < NCH) load_stage(i + 2, (i + 2) % 3);
        GEMM_COMPUTE(smb + st * STAGE_SZ);
    }

    // epilogue: dequant + bias + gelu -> d_hf (fp32)
#pragma unroll
    for (int mi = 0; mi < 2; mi++)
#pragma unroll
        for (int s = 0; s < 4; s++) {
            int cl = warp_n * 32 + s * 8 + ((lane & 3) << 1);
            float sc0 = s_sc[cl], sc1 = s_sc[cl + 1];
            float b0v = s_bias[cl], b1v = s_bias[cl + 1];
#pragma unroll
            for (int hh = 0; hh < 2; hh++) {
                int rl = warp_m * 32 + mi * 16 + (lane >> 2) + hh * 8;
                float srow = s_sx[rl];
                float f0 = 16384.0f * (float)S1[mi][s][hh * 2]     + 128.0f * (float)S2[mi][s][hh * 2];
                float f1 = 16384.0f * (float)S1[mi][s][hh * 2 + 1] + 128.0f * (float)S2[mi][s][hh * 2 + 1];
                float2 v;
                v.x = gelu_exact(f0 * (srow * sc0) + b0v);
                v.y = gelu_exact(f1 * (srow * sc1) + b1v);
                *(float2*)(d_hf + (size_t)(row0 + rl) * D_FF + n0 + cl) = v;
            }
        }
}

// ---------------- GEMM2: y = h @ W2_g + b2_g (int8 digits) ----------------
__global__ __launch_bounds__(512, 1)
void gemm2_imma(const float* __restrict__ sb2, const float* __restrict__ eb2) {
    extern __shared__ char sm[];
    __shared__ float s_sh[128];
    __shared__ float s_bias[128];
    __shared__ float s_sc[128];
    uint32_t smb = smem_u32(sm);
    int tid = threadIdx.x, lane = tid & 31, wid = tid >> 5;
    int warp_m = wid & 3, warp_n = wid >> 2;
    int rb = blockIdx.y, nb = blockIdx.x;
    int row0 = rb * 128, n0 = nb * 128;
    if (row0 >= d_est[N_EXP]) return;
    int g = 0;
    if (row0 >= EXP_BASE) {
        int e = 0;
#pragma unroll
        for (int i = 1; i < N_EXP; i++) if (row0 >= d_est[i]) e = i;
        g = e + 1;
    }
    const float* bias = (g == 0) ? sb2 : (eb2 + (size_t)(g - 1) * D_MODEL);
    if (tid < 128) {
        s_sh[tid] = d_sh[row0 + tid];
        s_bias[tid] = bias[n0 + tid];
        s_sc[tid] = d_sw2[g * D_MODEL + n0 + tid];
    }
    __syncthreads();

    const signed char* wq1 = d_w2q1 + ((size_t)g * D_MODEL + n0) * D_FF;
    const signed char* wq0 = d_w2q0 + ((size_t)g * D_MODEL + n0) * D_FF;

    int S1[2][4][4], S2[2][4][4];
#pragma unroll
    for (int a = 0; a < 2; a++)
#pragma unroll
        for (int b = 0; b < 4; b++)
#pragma unroll
            for (int c = 0; c < 4; c++) { S1[a][b][c] = 0; S2[a][b][c] = 0; }

    auto load_stage = [&](int i, int st) {
        uint32_t bb = smb + st * STAGE_SZ;
#pragma unroll
        for (int j = 0; j < 2; j++) {
            int ch = tid * 2 + j; int r = ch >> 3, c = ch & 7;
            size_t so = (size_t)(row0 + r) * D_FF + i * 128 + c * 16;
            uint32_t dsw = bb + r * 128 + ((c ^ (r & 7)) << 4);
            cpa(dsw, d_hq1 + so, 16);
            cpa(dsw + 16384, d_hq0 + so, 16);
        }
#pragma unroll
        for (int j = 0; j < 2; j++) {
            int ch = tid * 2 + j; int r = ch >> 3, c = ch & 7;
            size_t so = (size_t)r * D_FF + i * 128 + c * 16;
            uint32_t dsw = bb + 32768 + r * 128 + ((c ^ (r & 7)) << 4);
            cpa(dsw, wq1 + so, 16);
            cpa(dsw + 16384, wq0 + so, 16);
        }
        CP_COMMIT();
    };

    const int NCH = D_FF / 128;  // 32
    load_stage(0, 0);
    load_stage(1, 1);
    for (int i = 0; i < NCH; i++) {
        int st = i % 3;
        if (i + 1 < NCH) CP_WAIT1(); else CP_WAIT0();
        __syncthreads();
        if (i + 2 < NCH) load_stage(i + 2, (i + 2) % 3);
        GEMM_COMPUTE(smb + st * STAGE_SZ);
    }

#pragma unroll
    for (int mi = 0; mi < 2; mi++)
#pragma unroll
        for (int s = 0; s < 4; s++) {
            int cl = warp_n * 32 + s * 8 + ((lane & 3) << 1);
            float sc0 = s_sc[cl], sc1 = s_sc[cl + 1];
            float b0v = s_bias[cl], b1v = s_bias[cl + 1];
#pragma unroll
            for (int hh = 0; hh < 2; hh++) {
                int rl = warp_m * 32 + mi * 16 + (lane >> 2) + hh * 8;
                float srow = s_sh[rl];
                float f0 = 16384.0f * (float)S1[mi][s][hh * 2]     + 128.0f * (float)S2[mi][s][hh * 2];
                float f1 = 16384.0f * (float)S1[mi][s][hh * 2 + 1] + 128.0f * (float)S2[mi][s][hh * 2 + 1];
                float2 v;
                v.x = f0 * (srow * sc0) + b0v;
                v.y = f1 * (srow * sc1) + b1v;
                *(float2*)(d_y + (size_t)(row0 + rl) * D_MODEL + n0 + cl) = v;
            }
        }
}

// ---------------- combine ----------------
__global__ void combine_kernel(float* __restrict__ out) {
    int t = blockIdx.x;
    int i = threadIdx.x;
    int s0 = d_slot0[t], s1 = d_slot1[t];
    float w0 = d_w0[t], w1 = d_w1v[t];
    float4 a  = *(const float4*)(d_y + (size_t)t  * D_MODEL + i * 4);
    float4 p0 = *(const float4*)(d_y + (size_t)s0 * D_MODEL + i * 4);
    float4 p1 = *(const float4*)(d_y + (size_t)s1 * D_MODEL + i * 4);
    float4 r;
    r.x = a.x + w0 * p0.x + w1 * p1.x;
    r.y = a.y + w0 * p0.y + w1 * p1.y;
    r.z = a.z + w0 * p0.z + w1 * p1.z;
    r.w = a.w + w0 * p0.w + w1 * p1.w;
    *(float4*)(out + (size_t)t * D_MODEL + i * 4) = r;
}

// ---------------- launch ----------------
extern "C" void kernel_launch(void* const* d_in, const int* in_sizes, int n_in,
                              void* d_out, int out_size) {
    const float* x   = (const float*)d_in[0];
    const float* sw1 = (const float*)d_in[1];
    const float* sb1 = (const float*)d_in[2];
    const float* sw2 = (const float*)d_in[3];
    const float* sb2 = (const float*)d_in[4];
    const float* rw  = (const float*)d_in[5];
    const float* rb  = (const float*)d_in[6];
    const float* ew1 = (const float*)d_in[7];
    const float* eb1 = (const float*)d_in[8];
    const float* ew2 = (const float*)d_in[9];
    const float* eb2 = (const float*)d_in[10];
    float* out = (float*)d_out;

    static bool attr_set = false;
    if (!attr_set) {
        cudaFuncSetAttribute(gemm1_imma, cudaFuncAttributeMaxDynamicSharedMemorySize, GEMM_SMEM);
        cudaFuncSetAttribute(gemm2_imma, cudaFuncAttributeMaxDynamicSharedMemorySize, GEMM_SMEM);
        attr_set = true;
    }

    init_kernel<<<(MAX_ROWS + 255) / 256, 256>>>();
    router_kernel<<<(T_TOK * 32 + 255) / 256, 256>>>(x, rw, rb);
    offsets_kernel<<<1, 32>>>();
    scatter_kernel<<<(T_TOK + 255) / 256, 256>>>();

    quant_x_kernel<<<T_TOK / 8, 256>>>(x);

    float *sw1s, *sw1i, *sw2s, *sw2i;
    cudaGetSymbolAddress((void**)&sw1s, d_sw1);
    cudaGetSymbolAddress((void**)&sw1i, d_sw1i);
    cudaGetSymbolAddress((void**)&sw2s, d_sw2);
    cudaGetSymbolAddress((void**)&sw2i, d_sw2i);
    colmax_kernel<<<dim3(D_FF / 256, 9), 256>>>(sw1, ew1, sw1s, sw1i, D_MODEL, D_FF);
    colmax_kernel<<<dim3(D_MODEL / 256, 9), 256>>>(sw2, ew2, sw2s, sw2i, D_FF, D_MODEL);

    signed char *w1q1, *w1q0, *w2q1, *w2q0;
    cudaGetSymbolAddress((void**)&w1q1, d_w1q1);
    cudaGetSymbolAddress((void**)&w1q0, d_w1q0);
    cudaGetSymbolAddress((void**)&w2q1, d_w2q1);
    cudaGetSymbolAddress((void**)&w2q0, d_w2q0);
    quantw_kernel<<<dim3(D_FF / 64, D_MODEL / 64, 9), 256>>>(sw1, ew1, sw1i, w1q1, w1q0, D_MODEL, D_FF);
    quantw_kernel<<<dim3(D_MODEL / 64, D_FF / 64, 9), 256>>>(sw2, ew2, sw2i, w2q1, w2q0, D_FF, D_MODEL);

    gemm1_imma<<<dim3(D_FF / 128, NRB), 512, GEMM_SMEM>>>(sb1, eb1);
    quant_h_kernel<<<MAX_ROWS, 256>>>();
    gemm2_imma<<<dim3(D_MODEL / 128, NRB), 512, GEMM_SMEM>>>(sb2, eb2);

    combine_kernel<<<T_TOK, 256>>>(out);
}